// round 1
// baseline (speedup 1.0000x reference)
#include <cuda_runtime.h>
#include <cstdint>

// ---------------- problem constants ----------------
#define NPTS   1000000
#define FB     2
#define FX     512
#define FY     512
#define FZ     64
#define FIN    64
#define FH     32
#define SCORE_T 0.1f
#define CENT_T  0.2f
#define MAXP    128            // MAX_TREES * B
#define GRID_CELLS (FB*FX*FY*FZ)   // 33,554,432
#define CCAP    4096

// ---------------- device scratch (module-load allocated, zero-init) ----------------
__device__ unsigned int       g_grid[GRID_CELLS];     // 0 == empty, else float bits of score
__device__ unsigned long long g_keys[NPTS];           // (score_bits<<32) | ~idx
__device__ unsigned char      g_flag[NPTS];           // peak flags (for P<128 fill path)
__device__ int                g_hist1[65536];
__device__ int                g_hist2[65536];
__device__ unsigned long long g_ckeys[CCAP];
__device__ int                g_peak_count;
__device__ int                g_ccount;
__device__ int                g_bin1;
__device__ int                g_above1;
__device__ unsigned int       g_thresh;

static __device__ __forceinline__ int cell_of(int b, int x, int y, int z) {
    return ((b * FX + x) * FY + y) * FZ + z;
}

// ---------------- K0: zero small scratch ----------------
__global__ void k_init() {
    int i = blockIdx.x * blockDim.x + threadIdx.x;
    if (i < 65536) { g_hist1[i] = 0; g_hist2[i] = 0; }
    if (i == 0) { g_peak_count = 0; g_ccount = 0; g_bin1 = -2; g_thresh = 0u; }
}

// ---------------- K1: MLP + scatter-max ----------------
__global__ void __launch_bounds__(256) k_mlp(
    const float* __restrict__ feats,
    const int*   __restrict__ cb, const int* __restrict__ cx,
    const int*   __restrict__ cy, const int* __restrict__ cz,
    const int*   __restrict__ mask,
    const float* __restrict__ W1, const float* __restrict__ b1,
    const float* __restrict__ W2, const float* __restrict__ b2,
    float* __restrict__ out_score)
{
    __shared__ float sW1[FIN * FH];
    __shared__ float sb1[FH];
    __shared__ float sW2[FH];
    __shared__ float sb2;
    int t = threadIdx.x;
    for (int i = t; i < FIN * FH; i += blockDim.x) sW1[i] = W1[i];
    if (t < FH) { sb1[t] = b1[t]; sW2[t] = W2[t]; }
    if (t == 0) sb2 = b2[0];
    __syncthreads();

    int i = blockIdx.x * blockDim.x + t;
    if (i >= NPTS) return;

    const float4* f4 = reinterpret_cast<const float4*>(feats + (size_t)i * FIN);

    float acc[FH];
    #pragma unroll
    for (int j = 0; j < FH; j++) acc[j] = sb1[j];

    #pragma unroll 4
    for (int c = 0; c < FIN / 4; c++) {
        float4 f = f4[c];
        const float4* w0 = reinterpret_cast<const float4*>(&sW1[(c * 4 + 0) * FH]);
        const float4* w1 = reinterpret_cast<const float4*>(&sW1[(c * 4 + 1) * FH]);
        const float4* w2 = reinterpret_cast<const float4*>(&sW1[(c * 4 + 2) * FH]);
        const float4* w3 = reinterpret_cast<const float4*>(&sW1[(c * 4 + 3) * FH]);
        #pragma unroll
        for (int jj = 0; jj < FH / 4; jj++) {
            float4 wa = w0[jj];
            acc[jj*4+0] = fmaf(f.x, wa.x, acc[jj*4+0]);
            acc[jj*4+1] = fmaf(f.x, wa.y, acc[jj*4+1]);
            acc[jj*4+2] = fmaf(f.x, wa.z, acc[jj*4+2]);
            acc[jj*4+3] = fmaf(f.x, wa.w, acc[jj*4+3]);
            float4 wb = w1[jj];
            acc[jj*4+0] = fmaf(f.y, wb.x, acc[jj*4+0]);
            acc[jj*4+1] = fmaf(f.y, wb.y, acc[jj*4+1]);
            acc[jj*4+2] = fmaf(f.y, wb.z, acc[jj*4+2]);
            acc[jj*4+3] = fmaf(f.y, wb.w, acc[jj*4+3]);
            float4 wc = w2[jj];
            acc[jj*4+0] = fmaf(f.z, wc.x, acc[jj*4+0]);
            acc[jj*4+1] = fmaf(f.z, wc.y, acc[jj*4+1]);
            acc[jj*4+2] = fmaf(f.z, wc.z, acc[jj*4+2]);
            acc[jj*4+3] = fmaf(f.z, wc.w, acc[jj*4+3]);
            float4 wd = w3[jj];
            acc[jj*4+0] = fmaf(f.w, wd.x, acc[jj*4+0]);
            acc[jj*4+1] = fmaf(f.w, wd.y, acc[jj*4+1]);
            acc[jj*4+2] = fmaf(f.w, wd.z, acc[jj*4+2]);
            acc[jj*4+3] = fmaf(f.w, wd.w, acc[jj*4+3]);
        }
    }

    float z = sb2;
    #pragma unroll
    for (int j = 0; j < FH; j++) z = fmaf(fmaxf(acc[j], 0.0f), sW2[j], z);

    float s = 1.0f / (1.0f + expf(-z));
    if (mask[i] == 0) s = 0.0f;
    out_score[i] = s;

    if (s > SCORE_T) {
        int cell = cell_of(cb[i], cx[i], cy[i], cz[i]);
        atomicMax(&g_grid[cell], __float_as_uint(s));
    }
}

// ---------------- K2: peak detect + key append + level-1 histogram ----------------
__global__ void __launch_bounds__(256) k_peak(
    const float* __restrict__ score,
    const int* __restrict__ cb, const int* __restrict__ cx,
    const int* __restrict__ cy, const int* __restrict__ cz)
{
    int i = blockIdx.x * blockDim.x + threadIdx.x;
    if (i >= NPTS) return;
    float s = score[i];
    if (!(s > SCORE_T)) return;
    unsigned sb = __float_as_uint(s);
    int b = cb[i], x = cx[i], y = cy[i], z = cz[i];

    unsigned hmax = 0u;
    #pragma unroll
    for (int dx = -1; dx <= 1; dx++) {
        int nx = x + dx;
        if ((unsigned)nx >= FX) continue;
        #pragma unroll
        for (int dy = -1; dy <= 1; dy++) {
            int ny = y + dy;
            if ((unsigned)ny >= FY) continue;
            const unsigned* p = &g_grid[((b * FX + nx) * FY + ny) * FZ];
            #pragma unroll
            for (int dz = -1; dz <= 1; dz++) {
                int nz = z + dz;
                if ((unsigned)nz >= FZ) continue;
                unsigned v = p[nz];
                hmax = v > hmax ? v : hmax;
            }
        }
    }
    if (hmax == sb && s > CENT_T) {
        int pos = atomicAdd(&g_peak_count, 1);
        g_keys[pos] = ((unsigned long long)sb << 32) | (unsigned)(~(unsigned)i);
        g_flag[i] = 1;
        atomicAdd(&g_hist1[sb >> 16], 1);
    }
}

// ---------------- K3: level-1 threshold scan (single block, 1024 thr) ----------------
__global__ void __launch_bounds__(1024) k_thresh1() {
    __shared__ int csum[1024];
    int t = threadIdx.x;
    int myOrig = 0;
    int base = t * 64;
    for (int b = 0; b < 64; b++) myOrig += g_hist1[base + b];
    csum[t] = myOrig;
    __syncthreads();
    // Hillis-Steele inclusive prefix
    for (int off = 1; off < 1024; off <<= 1) {
        int v = (t >= off) ? csum[t - off] : 0;
        __syncthreads();
        csum[t] += v;
        __syncthreads();
    }
    int total = csum[1023];
    if (total < MAXP) {
        if (t == 0) { g_bin1 = -1; g_above1 = 0; }
        return;
    }
    int above = total - csum[t];   // strictly above my chunk
    if (above < MAXP && above + myOrig >= MAXP) {
        int run = above;
        for (int b = base + 63; b >= base; b--) {
            int h = g_hist1[b];
            if (run + h >= MAXP) { g_bin1 = b; g_above1 = run; break; }
            run += h;
        }
    }
}

// ---------------- K4: level-2 histogram (grid-wide over keys) ----------------
__global__ void __launch_bounds__(256) k_hist2() {
    int i = blockIdx.x * blockDim.x + threadIdx.x;
    int n = g_peak_count;
    int b1 = g_bin1;
    if (b1 < 0 || i >= n) return;
    unsigned sb = (unsigned)(g_keys[i] >> 32);
    if ((int)(sb >> 16) == b1) atomicAdd(&g_hist2[sb & 0xFFFFu], 1);
}

// ---------------- K5: level-2 threshold scan ----------------
__global__ void __launch_bounds__(1024) k_thresh2() {
    __shared__ int csum[1024];
    int t = threadIdx.x;
    int b1 = g_bin1;
    if (b1 < 0) { if (t == 0) g_thresh = 0u; return; }
    int above1 = g_above1;
    int myOrig = 0;
    int base = t * 64;
    for (int b = 0; b < 64; b++) myOrig += g_hist2[base + b];
    csum[t] = myOrig;
    __syncthreads();
    for (int off = 1; off < 1024; off <<= 1) {
        int v = (t >= off) ? csum[t - off] : 0;
        __syncthreads();
        csum[t] += v;
        __syncthreads();
    }
    int total = csum[1023];
    int above = above1 + (total - csum[t]);
    if (above < MAXP && above + myOrig >= MAXP) {
        int run = above;
        for (int b = base + 63; b >= base; b--) {
            int h = g_hist2[b];
            if (run + h >= MAXP) {
                g_thresh = ((unsigned)b1 << 16) | (unsigned)b;
                break;
            }
            run += h;
        }
    }
}

// ---------------- K6: compact survivors ----------------
__global__ void __launch_bounds__(256) k_compact() {
    int i = blockIdx.x * blockDim.x + threadIdx.x;
    int n = g_peak_count;
    if (i >= n) return;
    unsigned long long key = g_keys[i];
    unsigned sb = (unsigned)(key >> 32);
    if (sb >= g_thresh) {
        int pos = atomicAdd(&g_ccount, 1);
        if (pos < CCAP) g_ckeys[pos] = key;
    }
}

// ---------------- K7: sort + emit outputs (single block) ----------------
__global__ void __launch_bounds__(1024) k_output(
    float* __restrict__ out,
    const int* __restrict__ cb, const int* __restrict__ cx,
    const int* __restrict__ cy, const int* __restrict__ cz)
{
    __shared__ unsigned long long sk[CCAP];
    __shared__ int fill[MAXP];
    __shared__ int sValid;
    int t = threadIdx.x;
    int M = g_ccount; if (M > CCAP) M = CCAP;
    for (int i = t; i < CCAP; i += 1024) sk[i] = (i < M) ? g_ckeys[i] : 0ULL;
    __syncthreads();

    // bitonic sort, descending
    for (int kk = 2; kk <= CCAP; kk <<= 1) {
        for (int j = kk >> 1; j > 0; j >>= 1) {
            for (int i = t; i < CCAP; i += 1024) {
                int ixj = i ^ j;
                if (ixj > i) {
                    unsigned long long a = sk[i], b = sk[ixj];
                    bool descBlock = ((i & kk) == 0);
                    if (descBlock ? (a < b) : (a > b)) { sk[i] = b; sk[ixj] = a; }
                }
            }
            __syncthreads();
        }
    }

    if (t == 0) {
        int valid = M < MAXP ? M : MAXP;
        sValid = valid;
        if (valid < MAXP) {  // P < 128: fill with smallest non-peak indices
            int need = MAXP - valid, got = 0;
            for (int i = 0; i < NPTS && got < need; i++)
                if (!g_flag[i]) { fill[valid + got] = i; got++; }
        }
    }
    __syncthreads();

    if (t < MAXP) {
        int valid = sValid;
        float sc; int idx;
        if (t < valid) {
            unsigned long long key = sk[t];
            sc  = __uint_as_float((unsigned)(key >> 32));
            idx = (int)(~(unsigned)(key & 0xFFFFFFFFu));
        } else {
            sc  = -1.0f;
            idx = fill[t];
        }
        out[NPTS + t]              = (float)idx;                 // peak_indices
        out[NPTS + MAXP + t]       = sc;                         // peak_scores
        float* pc = out + NPTS + 2 * MAXP + (size_t)t * 4;       // peak_coords
        pc[0] = (float)cb[idx];
        pc[1] = (float)cx[idx];
        pc[2] = (float)cy[idx];
        pc[3] = (float)cz[idx];
    }
}

// ---------------- K8: cleanup touched state for next replay ----------------
__global__ void __launch_bounds__(256) k_cleanup(
    const float* __restrict__ score,
    const int* __restrict__ cb, const int* __restrict__ cx,
    const int* __restrict__ cy, const int* __restrict__ cz)
{
    int i = blockIdx.x * blockDim.x + threadIdx.x;
    if (i >= NPTS) return;
    g_flag[i] = 0;
    float s = score[i];
    if (s > SCORE_T) {
        g_grid[cell_of(cb[i], cx[i], cy[i], cz[i])] = 0u;
    }
}

// ---------------- launch ----------------
extern "C" void kernel_launch(void* const* d_in, const int* in_sizes, int n_in,
                              void* d_out, int out_size) {
    const float* feats = (const float*)d_in[0];
    const int*   cb    = (const int*)  d_in[1];
    const int*   cx    = (const int*)  d_in[2];
    const int*   cy    = (const int*)  d_in[3];
    const int*   cz    = (const int*)  d_in[4];
    const int*   mask  = (const int*)  d_in[5];
    const float* W1    = (const float*)d_in[6];
    const float* b1    = (const float*)d_in[7];
    const float* W2    = (const float*)d_in[8];
    const float* b2    = (const float*)d_in[9];
    float* out = (float*)d_out;

    const int NB = (NPTS + 255) / 256;

    k_init<<<256, 256>>>();
    k_mlp<<<NB, 256>>>(feats, cb, cx, cy, cz, mask, W1, b1, W2, b2, out);
    k_peak<<<NB, 256>>>(out, cb, cx, cy, cz);
    k_thresh1<<<1, 1024>>>();
    k_hist2<<<NB, 256>>>();
    k_thresh2<<<1, 1024>>>();
    k_compact<<<NB, 256>>>();
    k_output<<<1, 1024>>>(out, cb, cx, cy, cz);
    k_cleanup<<<NB, 256>>>(out, cb, cx, cy, cz);
}

// round 3
// speedup vs baseline: 1.4475x; 1.4475x over previous
#include <cuda_runtime.h>
#include <cstdint>

// ---------------- problem constants ----------------
#define NPTS   1000000
#define FX     512
#define FY     512
#define FZ     64
#define FIN    64
#define FH     32
#define SCORE_T 0.1f
#define CENT_T  0.2f
#define MAXP    128            // MAX_TREES * B
#define GRID_CELLS (2*FX*FY*FZ)   // 33,554,432
#define CCAP    1024
#define BIN1_BASE 0x3E4Cu      // (float_bits(0.2) >> 16); peak scores are in (0.2, 1.0)
#define NBIN1  512
#define NBIN2  4096

// ---------------- device scratch (module-load allocated, zero-init) ----------------
__device__ unsigned int       g_grid[GRID_CELLS];     // 0 == empty, else float bits of score
__device__ int                g_cell[NPTS];           // packed cell index per point
__device__ unsigned long long g_keys[NPTS];           // (score_bits<<32) | ~idx
__device__ unsigned char      g_flag[NPTS];           // peak flags (for P<128 fill path)
__device__ __align__(16) int  g_hist1[NBIN1];
__device__ __align__(16) int  g_hist2[NBIN2];
__device__ unsigned long long g_ckeys[CCAP];
__device__ int                g_peak_count;
__device__ int                g_ccount;
__device__ int                g_bin1;
__device__ int                g_above1;
__device__ unsigned int       g_thresh;

// ---------------- f32x2 helpers ----------------
__device__ __forceinline__ unsigned long long pk2(float x) {
    unsigned long long r; unsigned xi = __float_as_uint(x);
    asm("mov.b64 %0, {%1, %1};" : "=l"(r) : "r"(xi));
    return r;
}
__device__ __forceinline__ void fma2(unsigned long long& d, unsigned long long a, unsigned long long b) {
    asm("fma.rn.f32x2 %0, %1, %2, %0;" : "+l"(d) : "l"(a), "l"(b));
}
__device__ __forceinline__ float2 up2(unsigned long long v) {
    unsigned a, b;
    asm("mov.b64 {%0, %1}, %2;" : "=r"(a), "=r"(b) : "l"(v));
    return make_float2(__uint_as_float(a), __uint_as_float(b));
}

// ---------------- K1: MLP (f32x2) + scatter-max + cell pack ----------------
__global__ void __launch_bounds__(256) k_mlp(
    const float* __restrict__ feats,
    const int*   __restrict__ cb, const int* __restrict__ cx,
    const int*   __restrict__ cy, const int* __restrict__ cz,
    const int*   __restrict__ mask,
    const float* __restrict__ W1, const float* __restrict__ b1,
    const float* __restrict__ W2, const float* __restrict__ b2,
    float* __restrict__ out_score)
{
    __shared__ __align__(16) float sW1[FIN * FH];
    __shared__ __align__(16) float sb1[FH];
    __shared__ float sW2[FH];
    __shared__ float sb2;
    int t = threadIdx.x;
    for (int i = t; i < FIN * FH; i += 256) sW1[i] = W1[i];
    if (t < FH) { sb1[t] = b1[t]; sW2[t] = W2[t]; }
    if (t == 0) sb2 = b2[0];
    __syncthreads();

    int i = blockIdx.x * 256 + t;
    if (i >= NPTS) return;

    unsigned long long acc[FH / 2];                       // acc[j] = hidden cols (2j, 2j+1)
    const unsigned long long* b1p = reinterpret_cast<const unsigned long long*>(sb1);
    #pragma unroll
    for (int j = 0; j < FH / 2; j++) acc[j] = b1p[j];

    const float4* f4 = reinterpret_cast<const float4*>(feats + (size_t)i * FIN);
    #pragma unroll
    for (int c4 = 0; c4 < FIN / 4; c4++) {
        float4 f = f4[c4];
        float fv[4] = { f.x, f.y, f.z, f.w };
        #pragma unroll
        for (int k = 0; k < 4; k++) {
            unsigned long long fp = pk2(fv[k]);
            const ulonglong2* w = reinterpret_cast<const ulonglong2*>(&sW1[(c4 * 4 + k) * FH]);
            #pragma unroll
            for (int q = 0; q < FH / 4; q++) {            // FIX: 8 ulonglong2 cover all 32 cols
                ulonglong2 ww = w[q];                     // floats 4q..4q+3
                fma2(acc[2 * q + 0], fp, ww.x);           // cols (4q, 4q+1)
                fma2(acc[2 * q + 1], fp, ww.y);           // cols (4q+2, 4q+3)
            }
        }
    }

    float z = sb2;
    #pragma unroll
    for (int j = 0; j < FH / 2; j++) {
        float2 a = up2(acc[j]);
        z = fmaf(fmaxf(a.x, 0.0f), sW2[2 * j],     z);
        z = fmaf(fmaxf(a.y, 0.0f), sW2[2 * j + 1], z);
    }

    float s = 1.0f / (1.0f + expf(-z));
    if (mask[i] == 0) s = 0.0f;
    out_score[i] = s;

    int cell = ((cb[i] * FX + cx[i]) * FY + cy[i]) * FZ + cz[i];
    g_cell[i] = cell;
    if (s > SCORE_T) atomicMax(&g_grid[cell], __float_as_uint(s));
}

// ---------------- K2: peak detect + warp-aggregated append + level-1 hist ----------------
__global__ void __launch_bounds__(256) k_peak(const float* __restrict__ score)
{
    int i = blockIdx.x * 256 + threadIdx.x;
    bool valid = (i < NPTS);
    float s = valid ? score[i] : 0.0f;
    unsigned sb = __float_as_uint(s);
    bool isPeak = false;

    if (valid && s > CENT_T) {
        int cell = g_cell[i];
        int z = cell & 63;
        int y = (cell >> 6) & 511;
        int x = (cell >> 15) & 511;
        int b = cell >> 24;
        unsigned hmax = 0u;
        #pragma unroll
        for (int dx = -1; dx <= 1; dx++) {
            int nx = x + dx;
            if ((unsigned)nx >= FX) continue;
            #pragma unroll
            for (int dy = -1; dy <= 1; dy++) {
                int ny = y + dy;
                if ((unsigned)ny >= FY) continue;
                const unsigned* p = &g_grid[((b * FX + nx) * FY + ny) * FZ];
                #pragma unroll
                for (int dz = -1; dz <= 1; dz++) {
                    int nz = z + dz;
                    if ((unsigned)nz >= FZ) continue;
                    unsigned v = p[nz];
                    hmax = v > hmax ? v : hmax;
                }
            }
        }
        isPeak = (hmax == sb);    // own cell included -> hmax >= sb
    }

    unsigned m = __ballot_sync(0xFFFFFFFFu, isPeak);
    int lane = threadIdx.x & 31;
    int base = 0;
    if (lane == 0 && m) base = atomicAdd(&g_peak_count, __popc(m));
    base = __shfl_sync(0xFFFFFFFFu, base, 0);
    if (isPeak) {
        int pos = base + __popc(m & ((1u << lane) - 1u));
        g_keys[pos] = ((unsigned long long)sb << 32) | (unsigned)(~(unsigned)i);
        g_flag[i] = 1;
        atomicAdd(&g_hist1[(sb >> 16) - BIN1_BASE], 1);
    }
}

// ---------------- K3: level-1 threshold scan (512 bins, coalesced) ----------------
__global__ void __launch_bounds__(NBIN1) k_thresh1() {
    __shared__ int csum[NBIN1];
    int t = threadIdx.x;
    int h = g_hist1[t];
    csum[t] = h;
    __syncthreads();
    for (int off = 1; off < NBIN1; off <<= 1) {
        int v = (t >= off) ? csum[t - off] : 0;
        __syncthreads();
        csum[t] += v;
        __syncthreads();
    }
    int total = csum[NBIN1 - 1];
    if (total < MAXP) {
        if (t == 0) { g_bin1 = -1; g_above1 = 0; }
        return;
    }
    int above = total - csum[t];     // strictly above bin t
    if (above < MAXP && above + h >= MAXP) { g_bin1 = t; g_above1 = above; }
}

// ---------------- K4: level-2 histogram over peaks in bin1 ----------------
__global__ void __launch_bounds__(256) k_hist2() {
    int i = blockIdx.x * 256 + threadIdx.x;
    int n = g_peak_count;
    int b1 = g_bin1;
    if (b1 < 0 || i >= n) return;
    unsigned sb = (unsigned)(g_keys[i] >> 32);
    if ((int)((sb >> 16) - BIN1_BASE) == b1)
        atomicAdd(&g_hist2[(sb >> 4) & 0xFFFu], 1);
}

// ---------------- K5: level-2 threshold scan (4096 bins, int4 coalesced) ----------------
__global__ void __launch_bounds__(1024) k_thresh2() {
    __shared__ int csum[1024];
    int t = threadIdx.x;
    int b1 = g_bin1;
    if (b1 < 0) { if (t == 0) g_thresh = 0u; return; }
    int4 v = reinterpret_cast<const int4*>(g_hist2)[t];
    int my = v.x + v.y + v.z + v.w;
    csum[t] = my;
    __syncthreads();
    for (int off = 1; off < 1024; off <<= 1) {
        int vv = (t >= off) ? csum[t - off] : 0;
        __syncthreads();
        csum[t] += vv;
        __syncthreads();
    }
    int total = csum[1023];
    int above = g_above1 + (total - csum[t]);
    if (above < MAXP && above + my >= MAXP) {
        int run = above;
        int hh[4] = { v.x, v.y, v.z, v.w };
        #pragma unroll
        for (int b = 3; b >= 0; b--) {
            if (run + hh[b] >= MAXP) {
                g_thresh = ((unsigned)(b1 + BIN1_BASE) << 16) | ((unsigned)(t * 4 + b) << 4);
                break;
            }
            run += hh[b];
        }
    }
}

// ---------------- K6: compact survivors (warp-aggregated) ----------------
__global__ void __launch_bounds__(256) k_compact() {
    int i = blockIdx.x * 256 + threadIdx.x;
    int n = g_peak_count;
    bool take = false;
    unsigned long long key = 0ULL;
    if (i < n) {
        key = g_keys[i];
        take = ((unsigned)(key >> 32) >= g_thresh);
    }
    unsigned m = __ballot_sync(0xFFFFFFFFu, take);
    int lane = threadIdx.x & 31;
    int base = 0;
    if (lane == 0 && m) base = atomicAdd(&g_ccount, __popc(m));
    base = __shfl_sync(0xFFFFFFFFu, base, 0);
    if (take) {
        int pos = base + __popc(m & ((1u << lane) - 1u));
        if (pos < CCAP) g_ckeys[pos] = key;
    }
}

// ---------------- K7: sort + emit outputs (single block) ----------------
__global__ void __launch_bounds__(1024) k_output(float* __restrict__ out)
{
    __shared__ unsigned long long sk[CCAP];
    __shared__ int fill[MAXP];
    __shared__ int sValid;
    int t = threadIdx.x;
    int M = g_ccount; if (M > CCAP) M = CCAP;
    sk[t] = (t < M) ? g_ckeys[t] : 0ULL;
    __syncthreads();

    // bitonic sort, descending (1024 elements, 1 per thread)
    for (int kk = 2; kk <= CCAP; kk <<= 1) {
        for (int j = kk >> 1; j > 0; j >>= 1) {
            int ixj = t ^ j;
            if (ixj > t) {
                unsigned long long a = sk[t], b = sk[ixj];
                bool desc = ((t & kk) == 0);
                if (desc ? (a < b) : (a > b)) { sk[t] = b; sk[ixj] = a; }
            }
            __syncthreads();
        }
    }

    if (t == 0) {
        int valid = M < MAXP ? M : MAXP;
        sValid = valid;
        if (valid < MAXP) {  // P < 128: fill with smallest non-peak indices
            int need = MAXP - valid, got = 0;
            for (int i = 0; i < NPTS && got < need; i++)
                if (!g_flag[i]) { fill[valid + got] = i; got++; }
        }
    }
    __syncthreads();

    if (t < MAXP) {
        int valid = sValid;
        float sc; int idx;
        if (t < valid) {
            unsigned long long key = sk[t];
            sc  = __uint_as_float((unsigned)(key >> 32));
            idx = (int)(~(unsigned)(key & 0xFFFFFFFFu));
        } else {
            sc  = -1.0f;
            idx = fill[t];
        }
        out[NPTS + t]        = (float)idx;                 // peak_indices
        out[NPTS + MAXP + t] = sc;                         // peak_scores
        int cell = g_cell[idx];
        float* pc = out + NPTS + 2 * MAXP + (size_t)t * 4; // peak_coords
        pc[0] = (float)(cell >> 24);
        pc[1] = (float)((cell >> 15) & 511);
        pc[2] = (float)((cell >> 6) & 511);
        pc[3] = (float)(cell & 63);
    }
}

// ---------------- K8: cleanup ALL touched state for next replay ----------------
__global__ void __launch_bounds__(256) k_cleanup(const float* __restrict__ score)
{
    int i = blockIdx.x * 256 + threadIdx.x;
    if (i < NBIN2) g_hist2[i] = 0;
    if (i < NBIN1) g_hist1[i] = 0;
    if (i == 0) { g_peak_count = 0; g_ccount = 0; g_bin1 = -2; g_thresh = 0u; }
    if (i >= NPTS) return;
    g_flag[i] = 0;
    float s = score[i];
    if (s > SCORE_T) g_grid[g_cell[i]] = 0u;
}

// ---------------- launch ----------------
extern "C" void kernel_launch(void* const* d_in, const int* in_sizes, int n_in,
                              void* d_out, int out_size) {
    const float* feats = (const float*)d_in[0];
    const int*   cb    = (const int*)  d_in[1];
    const int*   cx    = (const int*)  d_in[2];
    const int*   cy    = (const int*)  d_in[3];
    const int*   cz    = (const int*)  d_in[4];
    const int*   mask  = (const int*)  d_in[5];
    const float* W1    = (const float*)d_in[6];
    const float* b1    = (const float*)d_in[7];
    const float* W2    = (const float*)d_in[8];
    const float* b2    = (const float*)d_in[9];
    float* out = (float*)d_out;

    const int NB = (NPTS + 255) / 256;

    k_mlp<<<NB, 256>>>(feats, cb, cx, cy, cz, mask, W1, b1, W2, b2, out);
    k_peak<<<NB, 256>>>(out);
    k_thresh1<<<1, NBIN1>>>();
    k_hist2<<<NB, 256>>>();
    k_thresh2<<<1, 1024>>>();
    k_compact<<<NB, 256>>>();
    k_output<<<1, 1024>>>(out);
    k_cleanup<<<NB, 256>>>(out);
}

// round 4
// speedup vs baseline: 1.5043x; 1.0392x over previous
#include <cuda_runtime.h>
#include <cstdint>

// ---------------- problem constants ----------------
#define NPTS   1000000
#define FX     512
#define FY     512
#define FZ     64
#define FIN    64
#define FH     32
#define SCORE_T 0.1f
#define CENT_T  0.2f
#define MAXP    128
#define CCAP    1024
#define BIN1_BASE 0x3E4Cu      // float_bits(0.2) >> 16 ; peak scores in (0.2, 1.0)
#define NBIN1  512
#define NBIN2  4096

// padded grid: [2][514][514][66], pad cells always 0
#define PX 514
#define PY 514
#define PZ 66
#define PCELLS (2*PX*PY*PZ)    // 34,873,872
#define DXS (PY*PZ)            // 33924
#define DYS (PZ)               // 66

// ---------------- device scratch (zero-init at module load) ----------------
__device__ unsigned int       g_grid[PCELLS];
__device__ int                g_cell[NPTS];          // packed original coords (b<<24|x<<15|y<<6|z)
__device__ int                g_touch[NPTS];         // padded cells with s>0.1 (to reset)
__device__ unsigned long long g_cand[NPTS];          // s>0.2 candidates: (sb<<32)|~idx
__device__ int                g_ccellp[NPTS];        // padded cell per candidate
__device__ unsigned long long g_keys[NPTS];          // peaks
__device__ __align__(16) int  g_hist1[NBIN1];
__device__ __align__(16) int  g_hist2[NBIN2];
__device__ unsigned long long g_ckeys[CCAP];
__device__ int g_touch_count, g_cand_count, g_peak_count, g_ccount;
__device__ int g_bin1, g_above1;
__device__ unsigned int g_thresh;

// ---------------- f32x2 helpers ----------------
__device__ __forceinline__ unsigned long long pk2(float x) {
    unsigned long long r; unsigned xi = __float_as_uint(x);
    asm("mov.b64 %0, {%1, %1};" : "=l"(r) : "r"(xi));
    return r;
}
__device__ __forceinline__ void fma2(unsigned long long& d, unsigned long long a, unsigned long long b) {
    asm("fma.rn.f32x2 %0, %1, %2, %0;" : "+l"(d) : "l"(a), "l"(b));
}
__device__ __forceinline__ float2 up2(unsigned long long v) {
    unsigned a, b;
    asm("mov.b64 {%0, %1}, %2;" : "=r"(a), "=r"(b) : "l"(v));
    return make_float2(__uint_as_float(a), __uint_as_float(b));
}

// epilogue: score -> output + grid scatter + list appends (warp-uniform ballots)
__device__ __forceinline__ void epilogue(
    int i, bool valid, float z,
    const int* __restrict__ cb, const int* __restrict__ cx,
    const int* __restrict__ cy, const int* __restrict__ cz,
    const int* __restrict__ mask, float* __restrict__ out_score)
{
    float s = 0.0f;
    int cellp = 0;
    unsigned sb = 0u;
    if (valid) {
        s = 1.0f / (1.0f + expf(-z));
        if (mask[i] == 0) s = 0.0f;
        out_score[i] = s;
        int b = cb[i], x = cx[i], y = cy[i], zc = cz[i];
        g_cell[i] = (b << 24) | (x << 15) | (y << 6) | zc;
        cellp = ((b * PX + x + 1) * PY + y + 1) * PZ + (zc + 1);
        sb = __float_as_uint(s);
    }
    int lane = threadIdx.x & 31;

    bool dep = valid && (s > SCORE_T);
    if (dep) atomicMax(&g_grid[cellp], sb);
    unsigned m = __ballot_sync(0xFFFFFFFFu, dep);
    int base = 0;
    if (lane == 0 && m) base = atomicAdd(&g_touch_count, __popc(m));
    base = __shfl_sync(0xFFFFFFFFu, base, 0);
    if (dep) g_touch[base + __popc(m & ((1u << lane) - 1u))] = cellp;

    bool cnd = valid && (s > CENT_T);
    unsigned m2 = __ballot_sync(0xFFFFFFFFu, cnd);
    int base2 = 0;
    if (lane == 0 && m2) base2 = atomicAdd(&g_cand_count, __popc(m2));
    base2 = __shfl_sync(0xFFFFFFFFu, base2, 0);
    if (cnd) {
        int pos = base2 + __popc(m2 & ((1u << lane) - 1u));
        g_cand[pos]   = ((unsigned long long)sb << 32) | (unsigned)(~(unsigned)i);
        g_ccellp[pos] = cellp;
    }
}

// ---------------- K1: MLP (f32x2, 2 points/thread) ----------------
__global__ void __launch_bounds__(256) k_mlp(
    const float* __restrict__ feats,
    const int*   __restrict__ cb, const int* __restrict__ cx,
    const int*   __restrict__ cy, const int* __restrict__ cz,
    const int*   __restrict__ mask,
    const float* __restrict__ W1, const float* __restrict__ b1,
    const float* __restrict__ W2, const float* __restrict__ b2,
    float* __restrict__ out_score)
{
    __shared__ __align__(16) float sW1[FIN * FH];
    __shared__ __align__(16) float sb1[FH];
    __shared__ float sW2[FH];
    __shared__ float sb2;
    int t = threadIdx.x;
    for (int i = t; i < FIN * FH; i += 256) sW1[i] = W1[i];
    if (t < FH) { sb1[t] = b1[t]; sW2[t] = W2[t]; }
    if (t == 0) sb2 = b2[0];
    __syncthreads();

    int p0 = blockIdx.x * 512 + t;
    int p1 = p0 + 256;
    bool v0 = (p0 < NPTS), v1 = (p1 < NPTS);

    unsigned long long acc0[FH / 2], acc1[FH / 2];
    const unsigned long long* b1p = reinterpret_cast<const unsigned long long*>(sb1);
    #pragma unroll
    for (int j = 0; j < FH / 2; j++) { acc0[j] = b1p[j]; acc1[j] = b1p[j]; }

    const float4* f40 = reinterpret_cast<const float4*>(feats + (size_t)(v0 ? p0 : 0) * FIN);
    const float4* f41 = reinterpret_cast<const float4*>(feats + (size_t)(v1 ? p1 : 0) * FIN);

    #pragma unroll 4
    for (int c4 = 0; c4 < FIN / 4; c4++) {
        float4 f0 = f40[c4];
        float4 f1 = f41[c4];
        float fa[4] = { f0.x, f0.y, f0.z, f0.w };
        float fb[4] = { f1.x, f1.y, f1.z, f1.w };
        #pragma unroll
        for (int k = 0; k < 4; k++) {
            unsigned long long fp0 = pk2(fa[k]);
            unsigned long long fp1 = pk2(fb[k]);
            const ulonglong2* w = reinterpret_cast<const ulonglong2*>(&sW1[(c4 * 4 + k) * FH]);
            #pragma unroll
            for (int q = 0; q < FH / 4; q++) {
                ulonglong2 ww = w[q];
                fma2(acc0[2 * q + 0], fp0, ww.x);
                fma2(acc0[2 * q + 1], fp0, ww.y);
                fma2(acc1[2 * q + 0], fp1, ww.x);
                fma2(acc1[2 * q + 1], fp1, ww.y);
            }
        }
    }

    float z0 = sb2, z1 = sb2;
    #pragma unroll
    for (int j = 0; j < FH / 2; j++) {
        float2 a0 = up2(acc0[j]);
        float2 a1 = up2(acc1[j]);
        float w0 = sW2[2 * j], w1 = sW2[2 * j + 1];
        z0 = fmaf(fmaxf(a0.x, 0.0f), w0, z0);
        z0 = fmaf(fmaxf(a0.y, 0.0f), w1, z0);
        z1 = fmaf(fmaxf(a1.x, 0.0f), w0, z1);
        z1 = fmaf(fmaxf(a1.y, 0.0f), w1, z1);
    }

    epilogue(p0, v0, z0, cb, cx, cy, cz, mask, out_score);
    epilogue(p1, v1, z1, cb, cx, cy, cz, mask, out_score);
}

// ---------------- K2: peak detect over candidate list ----------------
__global__ void __launch_bounds__(256) k_peak()
{
    int n = g_cand_count;
    int stride = gridDim.x * blockDim.x;
    for (int i = blockIdx.x * blockDim.x + threadIdx.x; ; i += stride) {
        bool valid = (i < n);
        unsigned long long key = 0ULL;
        unsigned sb = 0u, hmax = 0u;
        if (valid) {
            key = g_cand[i];
            sb  = (unsigned)(key >> 32);
            int cp = g_ccellp[i];
            #pragma unroll
            for (int dx = -1; dx <= 1; dx++) {
                #pragma unroll
                for (int dy = -1; dy <= 1; dy++) {
                    const unsigned* p = &g_grid[cp + dx * DXS + dy * DYS];
                    unsigned a = p[-1], b = p[0], c = p[1];
                    unsigned mx = a > b ? a : b;
                    mx = c > mx ? c : mx;
                    hmax = mx > hmax ? mx : hmax;
                }
            }
        }
        bool isPeak = valid && (hmax == sb);
        unsigned m = __ballot_sync(0xFFFFFFFFu, isPeak);
        int lane = threadIdx.x & 31;
        int base = 0;
        if (lane == 0 && m) base = atomicAdd(&g_peak_count, __popc(m));
        base = __shfl_sync(0xFFFFFFFFu, base, 0);
        if (isPeak) {
            g_keys[base + __popc(m & ((1u << lane) - 1u))] = key;
            atomicAdd(&g_hist1[(sb >> 16) - BIN1_BASE], 1);
        }
        if (i >= n) break;   // all lanes exit together after full strides
        if (i + stride >= n && ((n + stride - 1) / stride) * stride <= i + stride) {}
        if (i + stride >= n + stride) break;
        if (i >= n - (i % 1 ) && false) break;
        // loop bound: exit when this iteration's base index already past n
        if (i - (int)(threadIdx.x & 0) >= n) break;
    }
}

// ---------------- K3: level-1 threshold scan ----------------
__global__ void __launch_bounds__(NBIN1) k_thresh1() {
    __shared__ int csum[NBIN1];
    int t = threadIdx.x;
    int h = g_hist1[t];
    csum[t] = h;
    __syncthreads();
    for (int off = 1; off < NBIN1; off <<= 1) {
        int v = (t >= off) ? csum[t - off] : 0;
        __syncthreads();
        csum[t] += v;
        __syncthreads();
    }
    int total = csum[NBIN1 - 1];
    if (total < MAXP) {
        if (t == 0) { g_bin1 = -1; g_above1 = 0; }
        return;
    }
    int above = total - csum[t];
    if (above < MAXP && above + h >= MAXP) { g_bin1 = t; g_above1 = above; }
}

// ---------------- K4: level-2 histogram over peaks in bin1 ----------------
__global__ void __launch_bounds__(256) k_hist2() {
    int n = g_peak_count;
    int b1 = g_bin1;
    if (b1 < 0) return;
    int stride = gridDim.x * blockDim.x;
    for (int i = blockIdx.x * blockDim.x + threadIdx.x; i < n; i += stride) {
        unsigned sb = (unsigned)(g_keys[i] >> 32);
        if ((int)((sb >> 16) - BIN1_BASE) == b1)
            atomicAdd(&g_hist2[(sb >> 4) & 0xFFFu], 1);
    }
}

// ---------------- K5: level-2 threshold scan ----------------
__global__ void __launch_bounds__(1024) k_thresh2() {
    __shared__ int csum[1024];
    int t = threadIdx.x;
    int b1 = g_bin1;
    if (b1 < 0) { if (t == 0) g_thresh = 0u; return; }
    int4 v = reinterpret_cast<const int4*>(g_hist2)[t];
    int my = v.x + v.y + v.z + v.w;
    csum[t] = my;
    __syncthreads();
    for (int off = 1; off < 1024; off <<= 1) {
        int vv = (t >= off) ? csum[t - off] : 0;
        __syncthreads();
        csum[t] += vv;
        __syncthreads();
    }
    int total = csum[1023];
    int above = g_above1 + (total - csum[t]);
    if (above < MAXP && above + my >= MAXP) {
        int run = above;
        int hh[4] = { v.x, v.y, v.z, v.w };
        #pragma unroll
        for (int b = 3; b >= 0; b--) {
            if (run + hh[b] >= MAXP) {
                g_thresh = ((unsigned)(b1 + BIN1_BASE) << 16) | ((unsigned)(t * 4 + b) << 4);
                break;
            }
            run += hh[b];
        }
    }
}

// ---------------- K6: compact survivors ----------------
__global__ void __launch_bounds__(256) k_compact() {
    int n = g_peak_count;
    unsigned th = g_thresh;
    int stride = gridDim.x * blockDim.x;
    for (int i = blockIdx.x * blockDim.x + threadIdx.x; ; i += stride) {
        bool take = false;
        unsigned long long key = 0ULL;
        if (i < n) {
            key = g_keys[i];
            take = ((unsigned)(key >> 32) >= th);
        }
        unsigned m = __ballot_sync(0xFFFFFFFFu, take);
        int lane = threadIdx.x & 31;
        int base = 0;
        if (lane == 0 && m) base = atomicAdd(&g_ccount, __popc(m));
        base = __shfl_sync(0xFFFFFFFFu, base, 0);
        if (take) {
            int pos = base + __popc(m & ((1u << lane) - 1u));
            if (pos < CCAP) g_ckeys[pos] = key;
        }
        if (i >= n) break;
    }
}

// ---------------- K7: sort + emit outputs (single block) ----------------
__global__ void __launch_bounds__(1024) k_output(float* __restrict__ out)
{
    __shared__ unsigned long long sk[CCAP];
    __shared__ int fill[MAXP];
    __shared__ int sValid;
    int t = threadIdx.x;
    int M = g_ccount; if (M > CCAP) M = CCAP;
    sk[t] = (t < M) ? g_ckeys[t] : 0ULL;
    __syncthreads();

    for (int kk = 2; kk <= CCAP; kk <<= 1) {
        for (int j = kk >> 1; j > 0; j >>= 1) {
            int ixj = t ^ j;
            if (ixj > t) {
                unsigned long long a = sk[t], b = sk[ixj];
                bool desc = ((t & kk) == 0);
                if (desc ? (a < b) : (a > b)) { sk[t] = b; sk[ixj] = a; }
            }
            __syncthreads();
        }
    }

    if (t == 0) {
        int valid = M < MAXP ? M : MAXP;
        sValid = valid;
        if (valid < MAXP) {  // practically never: fill with smallest non-peak indices
            int need = MAXP - valid, got = 0;
            for (int i = 0; i < NPTS && got < need; i++) {
                bool isP = false;
                for (int q = 0; q < valid; q++) {
                    int pidx = (int)(~(unsigned)(sk[q] & 0xFFFFFFFFu));
                    if (pidx == i) { isP = true; break; }
                }
                if (!isP) { fill[valid + got] = i; got++; }
            }
        }
        // reset counters no longer needed downstream
        g_peak_count = 0; g_ccount = 0; g_bin1 = -2; g_thresh = 0u; g_cand_count = 0;
    }
    __syncthreads();

    if (t < MAXP) {
        int valid = sValid;
        float sc; int idx;
        if (t < valid) {
            unsigned long long key = sk[t];
            sc  = __uint_as_float((unsigned)(key >> 32));
            idx = (int)(~(unsigned)(key & 0xFFFFFFFFu));
        } else {
            sc  = -1.0f;
            idx = fill[t];
        }
        out[NPTS + t]        = (float)idx;
        out[NPTS + MAXP + t] = sc;
        int cell = g_cell[idx];
        float* pc = out + NPTS + 2 * MAXP + (size_t)t * 4;
        pc[0] = (float)(cell >> 24);
        pc[1] = (float)((cell >> 15) & 511);
        pc[2] = (float)((cell >> 6) & 511);
        pc[3] = (float)(cell & 63);
    }
}

// ---------------- K8: cleanup grid via touch list + clear hists ----------------
__global__ void __launch_bounds__(256) k_cleanup()
{
    int tn = g_touch_count;
    int stride = gridDim.x * blockDim.x;
    int i0 = blockIdx.x * blockDim.x + threadIdx.x;
    for (int i = i0; i < NBIN2; i += stride) g_hist2[i] = 0;
    for (int i = i0; i < NBIN1; i += stride) g_hist1[i] = 0;
    for (int i = i0; i < tn; i += stride) g_grid[g_touch[i]] = 0u;
}

// ---------------- K9: final counter reset (after cleanup consumed touch_count) ----------
__global__ void k_reset() {
    if (threadIdx.x == 0) g_touch_count = 0;
}

// ---------------- launch ----------------
extern "C" void kernel_launch(void* const* d_in, const int* in_sizes, int n_in,
                              void* d_out, int out_size) {
    const float* feats = (const float*)d_in[0];
    const int*   cb    = (const int*)  d_in[1];
    const int*   cx    = (const int*)  d_in[2];
    const int*   cy    = (const int*)  d_in[3];
    const int*   cz    = (const int*)  d_in[4];
    const int*   mask  = (const int*)  d_in[5];
    const float* W1    = (const float*)d_in[6];
    const float* b1    = (const float*)d_in[7];
    const float* W2    = (const float*)d_in[8];
    const float* b2    = (const float*)d_in[9];
    float* out = (float*)d_out;

    k_mlp<<<(NPTS + 511) / 512, 256>>>(feats, cb, cx, cy, cz, mask, W1, b1, W2, b2, out);
    k_peak<<<1024, 256>>>();
    k_thresh1<<<1, NBIN1>>>();
    k_hist2<<<512, 256>>>();
    k_thresh2<<<1, 1024>>>();
    k_compact<<<512, 256>>>();
    k_output<<<1, 1024>>>(out);
    k_cleanup<<<1024, 256>>>();
    k_reset<<<1, 32>>>();
}